// round 1
// baseline (speedup 1.0000x reference)
#include <cuda_runtime.h>
#include <cuda_bf16.h>

#define NTIME  4096
#define NBATCH 4096
#define NEXTRA 256

// One thread per (query q, batch column b), b fastest for coalescing of
// t / out / times-row-0 / times-row-last.
//
// searchsorted(side='right') via interpolation search on the sorted column,
// tracking bracket values so the final times[] gathers are free.
__global__ __launch_bounds__(256, 8)
void ts_interp_kernel(const float* __restrict__ times,
                      const float* __restrict__ values,
                      const float* __restrict__ t,
                      float* __restrict__ out)
{
    const int gid = blockIdx.x * blockDim.x + threadIdx.x;
    if (gid >= NEXTRA * NBATCH) return;
    const int b = gid & (NBATCH - 1);

    const float tq = __ldg(&t[gid]);
    const float ta = __ldg(&times[b]);                                   // times[0, b]
    const float tb = __ldg(&times[(size_t)(NTIME - 1) * NBATCH + b]);    // times[NTIME-1, b]

    // Edge case: counts == 0 (tq < times[0]) or counts == NTIME (tq >= times[-1]).
    // Both give gi = counts % NTIME == 0 -> torch wrap: idx = NTIME-1, sidx = NTIME-2.
    if (tq < ta || tq >= tb) {
        const float t1 = tb;
        const float t0 = __ldg(&times [(size_t)(NTIME - 2) * NBATCH + b]);
        const float v1 = __ldg(&values[(size_t)(NTIME - 1) * NBATCH + b]);
        const float v0 = __ldg(&values[(size_t)(NTIME - 2) * NBATCH + b]);
        const float s  = (v1 - v0) / (t1 - t0);
        out[gid] = v1 + s * (tq - t1);
        return;
    }

    // Invariant: times[lo] <= tq < times[hi]; tlo = times[lo], thi = times[hi].
    int   lo = 0,  hi = NTIME - 1;
    float tlo = ta, thi = tb;

    int iter = 0;
    while (hi - lo > 1) {
        int mid;
        if (iter < 6) {
            // Interpolation guess; clamped strictly inside so the bracket
            // shrinks by >= 1 every iteration regardless of data.
            const float f = (tq - tlo) / (thi - tlo);
            mid = lo + 1 + (int)(f * (float)(hi - lo - 1));
            mid = max(lo + 1, min(mid, hi - 1));
        } else {
            mid = (lo + hi) >> 1;   // guaranteed-log fallback
        }
        const float tm = __ldg(&times[(size_t)mid * NBATCH + b]);
        if (tm <= tq) { lo = mid; tlo = tm; }   // '<=' == searchsorted side='right'
        else          { hi = mid; thi = tm; }
        ++iter;
    }

    // gi = hi = lo+1; idx = lo; t0 = tlo = times[lo], t1 = thi = times[hi] (free).
    const float v0 = __ldg(&values[(size_t)lo * NBATCH + b]);
    const float v1 = __ldg(&values[(size_t)hi * NBATCH + b]);
    const float s  = (v1 - v0) / (thi - tlo);
    out[gid] = v0 + s * (tq - tlo);
}

extern "C" void kernel_launch(void* const* d_in, const int* in_sizes, int n_in,
                              void* d_out, int out_size)
{
    // Expected order per metadata: times (16M), values (16M), t (1M).
    // Defensive: identify t by its element count; times/values keep their
    // relative order among the remaining inputs.
    const float* times  = nullptr;
    const float* values = nullptr;
    const float* tq     = nullptr;
    for (int i = 0; i < n_in; ++i) {
        if (in_sizes[i] == NEXTRA * NBATCH && tq == nullptr) {
            tq = (const float*)d_in[i];
        } else if (times == nullptr) {
            times = (const float*)d_in[i];
        } else if (values == nullptr) {
            values = (const float*)d_in[i];
        }
    }

    float* out = (float*)d_out;
    const int total   = NEXTRA * NBATCH;
    const int threads = 256;
    const int blocks  = (total + threads - 1) / threads;
    ts_interp_kernel<<<blocks, threads>>>(times, values, tq, out);
}